// round 1
// baseline (speedup 1.0000x reference)
#include <cuda_runtime.h>
#include <float.h>

// Problem constants
#define BB   16
#define CC   512
#define HWN  1024          // H*W
#define NN   16384         // B*H*W
#define DD   256
#define KK   8192

// Scratch (device globals; no allocation allowed)
__device__ float g_flat[NN * DD];   // projected latents [N, D]
__device__ float g_se[KK];          // sum(emb^2) per code
__device__ float g_sf[NN];          // sum(flat^2) per row
__device__ int   g_idx[NN];         // argmin indices

// ---------------------------------------------------------------------------
// Kernel 1: projection GEMM. flat[n,d] = sum_c z[b,c,hw]*w[d,c] + bias[d]
// n = b*1024 + hw. Tiles: 64 rows x 64 cols, k-chunk 32, 256 threads, 4x4 micro.
// ---------------------------------------------------------------------------
__global__ void proj_kernel(const float* __restrict__ z,
                            const float* __restrict__ w,
                            const float* __restrict__ bp) {
    __shared__ float Zs[32][64];    // [c][n_local]
    __shared__ float Ws[32][65];    // [c][d_local], padded
    const int r0  = blockIdx.x * 64;
    const int d0  = blockIdx.y * 64;
    const int b   = r0 >> 10;
    const int hw0 = r0 & 1023;
    const int tid = threadIdx.x;
    const int ty  = tid >> 4;       // 0..15 -> row group
    const int tx  = tid & 15;       // 0..15 -> col group

    float acc[4][4];
#pragma unroll
    for (int i = 0; i < 4; i++)
#pragma unroll
        for (int j = 0; j < 4; j++) acc[i][j] = 0.0f;

    for (int c0 = 0; c0 < CC; c0 += 32) {
        for (int e = tid; e < 32 * 64; e += 256) {
            int cc = e >> 6, rr = e & 63;
            Zs[cc][rr] = z[((size_t)(b * CC + c0 + cc) << 10) + hw0 + rr];
        }
        for (int e = tid; e < 32 * 64; e += 256) {
            int dd = e >> 5, cc = e & 31;
            Ws[cc][dd] = w[(size_t)(d0 + dd) * CC + c0 + cc];
        }
        __syncthreads();
#pragma unroll
        for (int cc = 0; cc < 32; cc++) {
            float zr[4], wv[4];
#pragma unroll
            for (int i = 0; i < 4; i++) zr[i] = Zs[cc][ty * 4 + i];
#pragma unroll
            for (int j = 0; j < 4; j++) wv[j] = Ws[cc][tx * 4 + j];
#pragma unroll
            for (int i = 0; i < 4; i++)
#pragma unroll
                for (int j = 0; j < 4; j++)
                    acc[i][j] = fmaf(zr[i], wv[j], acc[i][j]);
        }
        __syncthreads();
    }
#pragma unroll
    for (int i = 0; i < 4; i++) {
        int n = r0 + ty * 4 + i;
#pragma unroll
        for (int j = 0; j < 4; j++) {
            int d = d0 + tx * 4 + j;
            g_flat[(size_t)n * DD + d] = __fadd_rn(acc[i][j], bp[d]);
        }
    }
}

// ---------------------------------------------------------------------------
// Kernel 2a/2b: row-wise sum of squares (warp per row)
// ---------------------------------------------------------------------------
__global__ void se_kernel(const float* __restrict__ emb) {
    int row = blockIdx.x * (blockDim.x >> 5) + (threadIdx.x >> 5);
    if (row >= KK) return;
    int lane = threadIdx.x & 31;
    const float* p = emb + (size_t)row * DD;
    float s = 0.0f;
    for (int d = lane; d < DD; d += 32) { float v = p[d]; s = fmaf(v, v, s); }
#pragma unroll
    for (int o = 16; o; o >>= 1) s += __shfl_xor_sync(0xffffffff, s, o);
    if (!lane) g_se[row] = s;
}

__global__ void sf_kernel() {
    int row = blockIdx.x * (blockDim.x >> 5) + (threadIdx.x >> 5);
    if (row >= NN) return;
    int lane = threadIdx.x & 31;
    const float* p = g_flat + (size_t)row * DD;
    float s = 0.0f;
    for (int d = lane; d < DD; d += 32) { float v = p[d]; s = fmaf(v, v, s); }
#pragma unroll
    for (int o = 16; o; o >>= 1) s += __shfl_xor_sync(0xffffffff, s, o);
    if (!lane) g_sf[row] = s;
}

// ---------------------------------------------------------------------------
// Kernel 3: fused distance GEMM + argmin.
// Block: 128 rows x all K (streamed in 64-k tiles). 256 threads.
// Micro: 8 rows (consecutive) x 4 k (strided by 16) per thread.
// d2 = (s_f + s_e) - 2*g  with explicit rounding to match the reference tree.
// ---------------------------------------------------------------------------
#define AM_ROWS   128
#define AM_KT     64
#define FT_PITCH  132      // 128 rows + 4 pad (float4-aligned)
#define ET_PITCH  260      // 256 d + 4 pad   (float4-aligned)
#define AM_SMEM   ((256 * FT_PITCH + AM_KT * ET_PITCH + AM_KT + AM_ROWS) * 4)

__global__ void argmin_kernel(const float* __restrict__ emb) {
    extern __shared__ float smem[];
    float* Ft  = smem;                        // [d][row]  256 x FT_PITCH
    float* Et  = Ft + 256 * FT_PITCH;         // [k][d]    64 x ET_PITCH
    float* ses = Et + AM_KT * ET_PITCH;       // [64]
    float* sfs = ses + AM_KT;                 // [128]

    const int r0  = blockIdx.x * AM_ROWS;
    const int tid = threadIdx.x;
    const int ty  = tid >> 4;                 // 0..15
    const int tx  = tid & 15;                 // 0..15
    const int rb  = ty * 8;                   // 8 consecutive rows

    // Load F tile transposed: Ft[d][n_local]
    for (int e = tid; e < (AM_ROWS * DD) / 4; e += 256) {
        int nl = e >> 6;                      // e*4 / 256
        int d0 = (e & 63) * 4;
        float4 v = *(const float4*)&g_flat[(size_t)(r0 + nl) * DD + d0];
        Ft[(d0 + 0) * FT_PITCH + nl] = v.x;
        Ft[(d0 + 1) * FT_PITCH + nl] = v.y;
        Ft[(d0 + 2) * FT_PITCH + nl] = v.z;
        Ft[(d0 + 3) * FT_PITCH + nl] = v.w;
    }
    if (tid < AM_ROWS) sfs[tid] = g_sf[r0 + tid];

    float best[8];
    int   bidx[8];
#pragma unroll
    for (int i = 0; i < 8; i++) { best[i] = FLT_MAX; bidx[i] = 0; }

    for (int k0 = 0; k0 < KK; k0 += AM_KT) {
        __syncthreads();
        // Load E tile (natural layout, padded): Et[k_local][d]
        for (int e = tid; e < (AM_KT * DD) / 4; e += 256) {
            int kl = e >> 6;
            int d0 = (e & 63) * 4;
            float4 v = *(const float4*)&emb[(size_t)(k0 + kl) * DD + d0];
            *(float4*)&Et[kl * ET_PITCH + d0] = v;
        }
        if (tid < AM_KT) ses[tid] = g_se[k0 + tid];
        __syncthreads();

        float acc[8][4];
#pragma unroll
        for (int i = 0; i < 8; i++)
#pragma unroll
            for (int j = 0; j < 4; j++) acc[i][j] = 0.0f;

#pragma unroll 2
        for (int d4 = 0; d4 < DD; d4 += 4) {
            float4 ev[4];
#pragma unroll
            for (int j = 0; j < 4; j++)
                ev[j] = *(const float4*)&Et[(tx + 16 * j) * ET_PITCH + d4];
#pragma unroll
            for (int q = 0; q < 4; q++) {
                int dd = d4 + q;
                float4 fa = *(const float4*)&Ft[dd * FT_PITCH + rb];
                float4 fb = *(const float4*)&Ft[dd * FT_PITCH + rb + 4];
                float fr[8] = {fa.x, fa.y, fa.z, fa.w, fb.x, fb.y, fb.z, fb.w};
#pragma unroll
                for (int j = 0; j < 4; j++) {
                    float e1 = (q == 0) ? ev[j].x : (q == 1) ? ev[j].y
                             : (q == 2) ? ev[j].z : ev[j].w;
#pragma unroll
                    for (int i = 0; i < 8; i++)
                        acc[i][j] = fmaf(fr[i], e1, acc[i][j]);
                }
            }
        }

        // Epilogue: d2 = (s_f + s_e) - 2*g, explicit rounding, ascending k
#pragma unroll
        for (int j = 0; j < 4; j++) {
            int kl = tx + 16 * j;
            float se = ses[kl];
            int kg = k0 + kl;
#pragma unroll
            for (int i = 0; i < 8; i++) {
                float t  = __fadd_rn(sfs[rb + i], se);
                float d2 = __fsub_rn(t, __fmul_rn(2.0f, acc[i][j]));
                if (d2 < best[i]) { best[i] = d2; bidx[i] = kg; }
            }
        }
    }

    // Cross-thread reduction per row (16 tx lanes per row), lexicographic
    __syncthreads();
    float* rv = smem;                          // [128][16]
    int*   ri = (int*)(smem + AM_ROWS * 16);
#pragma unroll
    for (int i = 0; i < 8; i++) {
        rv[(rb + i) * 16 + tx] = best[i];
        ri[(rb + i) * 16 + tx] = bidx[i];
    }
    __syncthreads();
    if (tid < AM_ROWS) {
        float bv = rv[tid * 16];
        int   bi = ri[tid * 16];
#pragma unroll
        for (int t = 1; t < 16; t++) {
            float v = rv[tid * 16 + t];
            int  ix = ri[tid * 16 + t];
            if (v < bv || (v == bv && ix < bi)) { bv = v; bi = ix; }
        }
        g_idx[r0 + tid] = bi;
    }
}

// ---------------------------------------------------------------------------
// Kernel 4: gather emb[idx] and write NCHW output (transpose via smem tile)
// ---------------------------------------------------------------------------
__global__ void gather_kernel(const float* __restrict__ emb,
                              float* __restrict__ out) {
    __shared__ float T[256][33];
    const int b   = blockIdx.y;
    const int hw0 = blockIdx.x * 32;
    const int tid = threadIdx.x;
    for (int e = tid; e < 32 * 256; e += 256) {
        int nl = e >> 8, d = e & 255;
        int idx = g_idx[b * HWN + hw0 + nl];
        T[d][nl] = emb[(size_t)idx * DD + d];
    }
    __syncthreads();
    for (int e = tid; e < 32 * 256; e += 256) {
        int d = e >> 5, hl = e & 31;
        out[((size_t)(b * DD + d) << 10) + hw0 + hl] = T[d][hl];
    }
}

__global__ void idx_out_kernel(float* __restrict__ out) {
    int n = blockIdx.x * 256 + threadIdx.x;
    if (n < NN) out[(size_t)NN * DD * 0 + 4194304 + n] = (float)g_idx[n];
}

// ---------------------------------------------------------------------------
extern "C" void kernel_launch(void* const* d_in, const int* in_sizes, int n_in,
                              void* d_out, int out_size) {
    const float* z   = (const float*)d_in[0];
    const float* w   = (const float*)d_in[1];
    const float* bp  = (const float*)d_in[2];
    const float* emb = (const float*)d_in[3];
    float* out = (float*)d_out;

    cudaFuncSetAttribute(argmin_kernel,
                         cudaFuncAttributeMaxDynamicSharedMemorySize, AM_SMEM);

    proj_kernel<<<dim3(NN / 64, DD / 64), 256>>>(z, w, bp);
    se_kernel<<<KK / 8, 256>>>(emb);
    sf_kernel<<<NN / 8, 256>>>();
    argmin_kernel<<<NN / AM_ROWS, 256, AM_SMEM>>>(emb);
    gather_kernel<<<dim3(HWN / 32, BB), 256>>>(emb, out);
    if (out_size >= 4194304 + NN)
        idx_out_kernel<<<NN / 256, 256>>>(out);
}

// round 4
// speedup vs baseline: 2.3655x; 2.3655x over previous
#include <cuda_runtime.h>
#include <cuda_bf16.h>
#include <float.h>
#include <cstdint>

#define BB   16
#define CC   512
#define HWN  1024
#define NN   16384
#define DD   256
#define KK   8192

__device__ float g_flat[NN * DD];
__device__ float g_se[KK];
__device__ float g_sf[NN];
__device__ int   g_idx[NN];
__device__ __nv_bfloat16 g_fhi[NN * DD];
__device__ __nv_bfloat16 g_flo[NN * DD];
__device__ __nv_bfloat16 g_ehi[KK * DD];
__device__ __nv_bfloat16 g_elo[KK * DD];

// ---------------------------------------------------------------------------
__device__ __forceinline__ uint32_t smem_to_u32(const void* p) {
    uint32_t a;
    asm("{ .reg .u64 t; cvta.to.shared.u64 t, %1; cvt.u32.u64 %0, t; }" : "=r"(a) : "l"(p));
    return a;
}
#define CP_ASYNC16(dst, src) \
    asm volatile("cp.async.cg.shared.global [%0], [%1], 16;" :: "r"(dst), "l"(src))
#define CP_COMMIT() asm volatile("cp.async.commit_group;" ::: "memory")
#define CP_WAIT0()  asm volatile("cp.async.wait_group 0;" ::: "memory")
#define CP_WAIT1()  asm volatile("cp.async.wait_group 1;" ::: "memory")

__device__ __forceinline__ void ldsm4(uint32_t addr, uint32_t r[4]) {
    asm volatile("ldmatrix.sync.aligned.m8n8.x4.shared.b16 {%0,%1,%2,%3}, [%4];"
                 : "=r"(r[0]), "=r"(r[1]), "=r"(r[2]), "=r"(r[3]) : "r"(addr));
}
__device__ __forceinline__ void mma16816(float c[4], const uint32_t a[4],
                                         uint32_t b0, uint32_t b1) {
    asm volatile(
        "mma.sync.aligned.m16n8k16.row.col.f32.bf16.bf16.f32 "
        "{%0,%1,%2,%3}, {%4,%5,%6,%7}, {%8,%9}, {%0,%1,%2,%3};"
        : "+f"(c[0]), "+f"(c[1]), "+f"(c[2]), "+f"(c[3])
        : "r"(a[0]), "r"(a[1]), "r"(a[2]), "r"(a[3]), "r"(b0), "r"(b1));
}

// ---------------------------------------------------------------------------
// Kernel 1: projection GEMM (fp32 SIMT)
// ---------------------------------------------------------------------------
__global__ void proj_kernel(const float* __restrict__ z,
                            const float* __restrict__ w,
                            const float* __restrict__ bp) {
    __shared__ float Zs[32][64];
    __shared__ float Ws[32][65];
    const int r0  = blockIdx.x * 64;
    const int d0  = blockIdx.y * 64;
    const int b   = r0 >> 10;
    const int hw0 = r0 & 1023;
    const int tid = threadIdx.x;
    const int ty  = tid >> 4;
    const int tx  = tid & 15;

    float acc[4][4];
#pragma unroll
    for (int i = 0; i < 4; i++)
#pragma unroll
        for (int j = 0; j < 4; j++) acc[i][j] = 0.0f;

    for (int c0 = 0; c0 < CC; c0 += 32) {
        for (int e = tid; e < 32 * 64; e += 256) {
            int cc = e >> 6, rr = e & 63;
            Zs[cc][rr] = z[((size_t)(b * CC + c0 + cc) << 10) + hw0 + rr];
        }
        for (int e = tid; e < 32 * 64; e += 256) {
            int dd = e >> 5, cc = e & 31;
            Ws[cc][dd] = w[(size_t)(d0 + dd) * CC + c0 + cc];
        }
        __syncthreads();
#pragma unroll
        for (int cc = 0; cc < 32; cc++) {
            float zr[4], wv[4];
#pragma unroll
            for (int i = 0; i < 4; i++) zr[i] = Zs[cc][ty * 4 + i];
#pragma unroll
            for (int j = 0; j < 4; j++) wv[j] = Ws[cc][tx * 4 + j];
#pragma unroll
            for (int i = 0; i < 4; i++)
#pragma unroll
                for (int j = 0; j < 4; j++)
                    acc[i][j] = fmaf(zr[i], wv[j], acc[i][j]);
        }
        __syncthreads();
    }
#pragma unroll
    for (int i = 0; i < 4; i++) {
        int n = r0 + ty * 4 + i;
#pragma unroll
        for (int j = 0; j < 4; j++) {
            int d = d0 + tx * 4 + j;
            g_flat[(size_t)n * DD + d] = __fadd_rn(acc[i][j], bp[d]);
        }
    }
}

// ---------------------------------------------------------------------------
// Row-wise sums of squares + hi/lo splits
// ---------------------------------------------------------------------------
__global__ void se_kernel(const float* __restrict__ emb) {
    int row = blockIdx.x * (blockDim.x >> 5) + (threadIdx.x >> 5);
    if (row >= KK) return;
    int lane = threadIdx.x & 31;
    const float* p = emb + (size_t)row * DD;
    float s = 0.0f;
    for (int d = lane; d < DD; d += 32) { float v = p[d]; s = fmaf(v, v, s); }
#pragma unroll
    for (int o = 16; o; o >>= 1) s += __shfl_xor_sync(0xffffffff, s, o);
    if (!lane) g_se[row] = s;
}

__global__ void sf_kernel() {
    int row = blockIdx.x * (blockDim.x >> 5) + (threadIdx.x >> 5);
    if (row >= NN) return;
    int lane = threadIdx.x & 31;
    const float* p = g_flat + (size_t)row * DD;
    float s = 0.0f;
    for (int d = lane; d < DD; d += 32) { float v = p[d]; s = fmaf(v, v, s); }
#pragma unroll
    for (int o = 16; o; o >>= 1) s += __shfl_xor_sync(0xffffffff, s, o);
    if (!lane) g_sf[row] = s;
}

__global__ void split_flat_kernel() {
    int i = blockIdx.x * 256 + threadIdx.x;
    if (i >= NN * DD / 4) return;
    float4 v = *(const float4*)&g_flat[i * 4];
    float xs[4] = {v.x, v.y, v.z, v.w};
#pragma unroll
    for (int j = 0; j < 4; j++) {
        __nv_bfloat16 hi = __float2bfloat16(xs[j]);
        __nv_bfloat16 lo = __float2bfloat16(xs[j] - __bfloat162float(hi));
        g_fhi[i * 4 + j] = hi;
        g_flo[i * 4 + j] = lo;
    }
}

__global__ void split_emb_kernel(const float* __restrict__ emb) {
    int i = blockIdx.x * 256 + threadIdx.x;
    if (i >= KK * DD / 4) return;
    float4 v = *(const float4*)&emb[i * 4];
    float xs[4] = {v.x, v.y, v.z, v.w};
#pragma unroll
    for (int j = 0; j < 4; j++) {
        __nv_bfloat16 hi = __float2bfloat16(xs[j]);
        __nv_bfloat16 lo = __float2bfloat16(xs[j] - __bfloat162float(hi));
        g_ehi[i * 4 + j] = hi;
        g_elo[i * 4 + j] = lo;
    }
}

// ---------------------------------------------------------------------------
// Kernel 3: distance GEMM + argmin via mma.sync bf16 (3-pass hi/lo).
// CTA = 128 rows x all 8192 codes. 8 warps (2x4), warp tile 64x64.
// A hi/lo resident in SMEM (pitch 528B). B streamed in 256-code x 32-k stages
// (hi+lo, pitch 80B), double-buffered cp.async. Per stage 3 sub-passes x 2 k16.
// Argmin folded into registers per 256-code column tile; final SMEM reduce.
// ---------------------------------------------------------------------------
#define APITCH  528
#define BPITCH  80
#define AHI_OFF 0
#define ALO_OFF 67584          // 128*528
#define B_OFF   135168
#define BMAT_SZ 20480          // 256*80
#define BBUF_SZ 40960
#define DS_SMEM (B_OFF + 2 * BBUF_SZ)   // 217088
#define NSTAGE  256            // 32 col-tiles * 8 k-chunks

__device__ __forceinline__ void load_bstage(uint32_t sb, int buf, int s, int tid) {
    const int ct = s >> 3;
    const int k0 = (s & 7) * 32;
    uint32_t dst = sb + B_OFF + buf * BBUF_SZ;
    const char* srch = (const char*)g_ehi;
    const char* srcl = (const char*)g_elo;
    size_t gbase = (size_t)ct * 256 * 512 + (size_t)k0 * 2;
#pragma unroll
    for (int i = 0; i < 4; i++) {
        int c = i * 256 + tid;            // 0..1023
        int row = c >> 2, ch = c & 3;
        uint32_t doff = row * BPITCH + ch * 16;
        size_t soff = gbase + (size_t)row * 512 + ch * 16;
        CP_ASYNC16(dst + doff, srch + soff);
        CP_ASYNC16(dst + BMAT_SZ + doff, srcl + soff);
    }
}

__global__ void __launch_bounds__(256, 1) dist_kernel() {
    extern __shared__ char smem[];
    const uint32_t sb = smem_to_u32(smem);
    const int tid = threadIdx.x;
    const int l   = tid & 31;
    const int w   = tid >> 5;
    const int wm  = w >> 2;          // 0..1
    const int wn  = w & 3;           // 0..3
    const int r0  = blockIdx.x * 128;

    // Prologue: resident A hi/lo (128 rows x 32 chunks each) + first B stage.
    // 4096 chunk indices; both hi and lo issued per index. (Round-3 bug was
    // i<32 here -> OOB rows + SMEM stomp.)
#pragma unroll 4
    for (int i = 0; i < 16; i++) {
        int c = i * 256 + tid;           // 0..4095
        int row = c >> 5, ch = c & 31;   // row 0..127, ch 0..31
        CP_ASYNC16(sb + AHI_OFF + row * APITCH + ch * 16,
                   (const char*)(g_fhi + (size_t)(r0 + row) * DD) + ch * 16);
        CP_ASYNC16(sb + ALO_OFF + row * APITCH + ch * 16,
                   (const char*)(g_flo + (size_t)(r0 + row) * DD) + ch * 16);
    }
    load_bstage(sb, 0, 0, tid);
    CP_COMMIT();

    // Per-thread invariant ldmatrix offsets
    const int arow = (l & 7) + ((l >> 3) & 1) * 8;
    const int aco  = (l >> 4);
    uint32_t aoff[4];
#pragma unroll
    for (int mt = 0; mt < 4; mt++)
        aoff[mt] = (wm * 64 + mt * 16 + arow) * APITCH + aco * 16;
    const int brow = (l & 7) + ((l >> 4) << 3);
    const int bco  = (l >> 3) & 1;
    uint32_t boff[4];
#pragma unroll
    for (int bt = 0; bt < 4; bt++)
        boff[bt] = (wn * 64 + bt * 16 + brow) * BPITCH + bco * 16;

    float sfv[4][2];
#pragma unroll
    for (int mt = 0; mt < 4; mt++)
#pragma unroll
        for (int h = 0; h < 2; h++)
            sfv[mt][h] = g_sf[r0 + wm * 64 + mt * 16 + (l >> 2) + h * 8];

    float acc[4][8][4];
#pragma unroll
    for (int mt = 0; mt < 4; mt++)
#pragma unroll
        for (int nt = 0; nt < 8; nt++)
#pragma unroll
            for (int q = 0; q < 4; q++) acc[mt][nt][q] = 0.0f;

    float best[4][2];
    int   bidx[4][2];
#pragma unroll
    for (int mt = 0; mt < 4; mt++)
#pragma unroll
        for (int h = 0; h < 2; h++) { best[mt][h] = FLT_MAX; bidx[mt][h] = 0; }

    for (int s = 0; s < NSTAGE; s++) {
        if (s + 1 < NSTAGE) {
            load_bstage(sb, (s + 1) & 1, s + 1, tid);
            CP_COMMIT();
            CP_WAIT1();
        } else {
            CP_WAIT0();
        }
        __syncthreads();

        const uint32_t bbase = sb + B_OFF + (s & 1) * BBUF_SZ;
        const int kc = (s & 7) * 4;       // A 16B-chunk base for this stage

#pragma unroll
        for (int sp = 0; sp < 3; sp++) {
            const uint32_t abase = sb + ((sp == 1) ? ALO_OFF : AHI_OFF);
            const uint32_t bmat  = bbase + ((sp == 2) ? BMAT_SZ : 0);
#pragma unroll
            for (int kk = 0; kk < 2; kk++) {
                uint32_t af[4][4];
#pragma unroll
                for (int mt = 0; mt < 4; mt++)
                    ldsm4(abase + aoff[mt] + (kc + kk * 2) * 16, af[mt]);
                uint32_t bf[4][4];
#pragma unroll
                for (int bt = 0; bt < 4; bt++)
                    ldsm4(bmat + boff[bt] + kk * 32, bf[bt]);
#pragma unroll
                for (int mt = 0; mt < 4; mt++)
#pragma unroll
                    for (int nt = 0; nt < 8; nt++)
                        mma16816(acc[mt][nt], af[mt],
                                 bf[nt >> 1][(nt & 1) * 2],
                                 bf[nt >> 1][(nt & 1) * 2 + 1]);
            }
        }

        if ((s & 7) == 7) {
            const int ct = s >> 3;
#pragma unroll
            for (int nt = 0; nt < 8; nt++) {
#pragma unroll
                for (int q = 0; q < 2; q++) {
                    int col = ct * 256 + wn * 64 + nt * 8 + (l & 3) * 2 + q;
                    float se = __ldg(&g_se[col]);
#pragma unroll
                    for (int mt = 0; mt < 4; mt++)
#pragma unroll
                        for (int h = 0; h < 2; h++) {
                            float g  = acc[mt][nt][h * 2 + q];
                            float d2 = __fsub_rn(__fadd_rn(sfv[mt][h], se),
                                                 __fmul_rn(2.0f, g));
                            if (d2 < best[mt][h]) { best[mt][h] = d2; bidx[mt][h] = col; }
                            acc[mt][nt][h * 2 + q] = 0.0f;
                        }
                }
            }
        }
        __syncthreads();
    }

    // Final per-row reduce (128 rows x 16 candidate threads), lexicographic
    float* rv = (float*)smem;
    int*   ri = (int*)(smem + 128 * 16 * 4);
    const int slot = wn * 4 + (l & 3);
#pragma unroll
    for (int mt = 0; mt < 4; mt++)
#pragma unroll
        for (int h = 0; h < 2; h++) {
            int rl = wm * 64 + mt * 16 + (l >> 2) + h * 8;
            rv[rl * 16 + slot] = best[mt][h];
            ri[rl * 16 + slot] = bidx[mt][h];
        }
    __syncthreads();
    if (tid < 128) {
        float bv = rv[tid * 16];
        int   bi = ri[tid * 16];
#pragma unroll
        for (int t = 1; t < 16; t++) {
            float v = rv[tid * 16 + t];
            int  ix = ri[tid * 16 + t];
            if (v < bv || (v == bv && ix < bi)) { bv = v; bi = ix; }
        }
        g_idx[r0 + tid] = bi;
    }
}

// ---------------------------------------------------------------------------
// Kernel 4: gather emb[idx] -> NCHW output
// ---------------------------------------------------------------------------
__global__ void gather_kernel(const float* __restrict__ emb,
                              float* __restrict__ out) {
    __shared__ float T[256][33];
    const int b   = blockIdx.y;
    const int hw0 = blockIdx.x * 32;
    const int tid = threadIdx.x;
    for (int e = tid; e < 32 * 256; e += 256) {
        int nl = e >> 8, d = e & 255;
        int idx = g_idx[b * HWN + hw0 + nl];
        T[d][nl] = emb[(size_t)idx * DD + d];
    }
    __syncthreads();
    for (int e = tid; e < 32 * 256; e += 256) {
        int d = e >> 5, hl = e & 31;
        out[((size_t)(b * DD + d) << 10) + hw0 + hl] = T[d][hl];
    }
}

__global__ void idx_out_kernel(float* __restrict__ out) {
    int n = blockIdx.x * 256 + threadIdx.x;
    if (n < NN) out[4194304 + n] = (float)g_idx[n];
}

// ---------------------------------------------------------------------------
extern "C" void kernel_launch(void* const* d_in, const int* in_sizes, int n_in,
                              void* d_out, int out_size) {
    const float* z   = (const float*)d_in[0];
    const float* w   = (const float*)d_in[1];
    const float* bp  = (const float*)d_in[2];
    const float* emb = (const float*)d_in[3];
    float* out = (float*)d_out;

    cudaFuncSetAttribute(dist_kernel,
                         cudaFuncAttributeMaxDynamicSharedMemorySize, DS_SMEM);

    proj_kernel<<<dim3(NN / 64, DD / 64), 256>>>(z, w, bp);
    se_kernel<<<KK / 8, 256>>>(emb);
    sf_kernel<<<NN / 8, 256>>>();
    split_flat_kernel<<<(NN * DD / 4) / 256, 256>>>();
    split_emb_kernel<<<(KK * DD / 4) / 256, 256>>>(emb);
    dist_kernel<<<NN / 128, 256, DS_SMEM>>>();
    gather_kernel<<<dim3(HWN / 32, BB), 256>>>(emb, out);
    if (out_size >= 4194304 + NN)
        idx_out_kernel<<<NN / 256, 256>>>(out);
}

// round 5
// speedup vs baseline: 2.4444x; 1.0334x over previous
#include <cuda_runtime.h>
#include <cuda_bf16.h>
#include <float.h>
#include <cstdint>

#define BB   16
#define CC   512
#define HWN  1024
#define NN   16384
#define DD   256
#define KK   8192

__device__ float g_flat[NN * DD];
__device__ float g_se[KK];
__device__ float g_sf[NN];
__device__ int   g_idx[NN];
__device__ __nv_bfloat16 g_fhi[NN * DD];
__device__ __nv_bfloat16 g_flo[NN * DD];
__device__ __nv_bfloat16 g_ehi[KK * DD];
__device__ __nv_bfloat16 g_elo[KK * DD];

// ---------------------------------------------------------------------------
__device__ __forceinline__ uint32_t smem_to_u32(const void* p) {
    uint32_t a;
    asm("{ .reg .u64 t; cvta.to.shared.u64 t, %1; cvt.u32.u64 %0, t; }" : "=r"(a) : "l"(p));
    return a;
}
#define CP_ASYNC16(dst, src) \
    asm volatile("cp.async.cg.shared.global [%0], [%1], 16;" :: "r"(dst), "l"(src))
#define CP_COMMIT() asm volatile("cp.async.commit_group;" ::: "memory")
#define CP_WAIT0()  asm volatile("cp.async.wait_group 0;" ::: "memory")

__device__ __forceinline__ void ldsm4(uint32_t addr, uint32_t r[4]) {
    asm volatile("ldmatrix.sync.aligned.m8n8.x4.shared.b16 {%0,%1,%2,%3}, [%4];"
                 : "=r"(r[0]), "=r"(r[1]), "=r"(r[2]), "=r"(r[3]) : "r"(addr));
}
__device__ __forceinline__ void mma16816(float c[4], const uint32_t a[4],
                                         uint32_t b0, uint32_t b1) {
    asm volatile(
        "mma.sync.aligned.m16n8k16.row.col.f32.bf16.bf16.f32 "
        "{%0,%1,%2,%3}, {%4,%5,%6,%7}, {%8,%9}, {%0,%1,%2,%3};"
        : "+f"(c[0]), "+f"(c[1]), "+f"(c[2]), "+f"(c[3])
        : "r"(a[0]), "r"(a[1]), "r"(a[2]), "r"(a[3]), "r"(b0), "r"(b1));
}

// ---------------------------------------------------------------------------
// Kernel 1: projection GEMM (fp32 SIMT)
// ---------------------------------------------------------------------------
__global__ void proj_kernel(const float* __restrict__ z,
                            const float* __restrict__ w,
                            const float* __restrict__ bp) {
    __shared__ float Zs[32][64];
    __shared__ float Ws[32][65];
    const int r0  = blockIdx.x * 64;
    const int d0  = blockIdx.y * 64;
    const int b   = r0 >> 10;
    const int hw0 = r0 & 1023;
    const int tid = threadIdx.x;
    const int ty  = tid >> 4;
    const int tx  = tid & 15;

    float acc[4][4];
#pragma unroll
    for (int i = 0; i < 4; i++)
#pragma unroll
        for (int j = 0; j < 4; j++) acc[i][j] = 0.0f;

    for (int c0 = 0; c0 < CC; c0 += 32) {
        for (int e = tid; e < 32 * 64; e += 256) {
            int cc = e >> 6, rr = e & 63;
            Zs[cc][rr] = z[((size_t)(b * CC + c0 + cc) << 10) + hw0 + rr];
        }
        for (int e = tid; e < 32 * 64; e += 256) {
            int dd = e >> 5, cc = e & 31;
            Ws[cc][dd] = w[(size_t)(d0 + dd) * CC + c0 + cc];
        }
        __syncthreads();
#pragma unroll
        for (int cc = 0; cc < 32; cc++) {
            float zr[4], wv[4];
#pragma unroll
            for (int i = 0; i < 4; i++) zr[i] = Zs[cc][ty * 4 + i];
#pragma unroll
            for (int j = 0; j < 4; j++) wv[j] = Ws[cc][tx * 4 + j];
#pragma unroll
            for (int i = 0; i < 4; i++)
#pragma unroll
                for (int j = 0; j < 4; j++)
                    acc[i][j] = fmaf(zr[i], wv[j], acc[i][j]);
        }
        __syncthreads();
    }
#pragma unroll
    for (int i = 0; i < 4; i++) {
        int n = r0 + ty * 4 + i;
#pragma unroll
        for (int j = 0; j < 4; j++) {
            int d = d0 + tx * 4 + j;
            g_flat[(size_t)n * DD + d] = __fadd_rn(acc[i][j], bp[d]);
        }
    }
}

// ---------------------------------------------------------------------------
// Row-wise sums of squares + hi/lo splits
// ---------------------------------------------------------------------------
__global__ void se_kernel(const float* __restrict__ emb) {
    int row = blockIdx.x * (blockDim.x >> 5) + (threadIdx.x >> 5);
    if (row >= KK) return;
    int lane = threadIdx.x & 31;
    const float* p = emb + (size_t)row * DD;
    float s = 0.0f;
    for (int d = lane; d < DD; d += 32) { float v = p[d]; s = fmaf(v, v, s); }
#pragma unroll
    for (int o = 16; o; o >>= 1) s += __shfl_xor_sync(0xffffffff, s, o);
    if (!lane) g_se[row] = s;
}

__global__ void sf_kernel() {
    int row = blockIdx.x * (blockDim.x >> 5) + (threadIdx.x >> 5);
    if (row >= NN) return;
    int lane = threadIdx.x & 31;
    const float* p = g_flat + (size_t)row * DD;
    float s = 0.0f;
    for (int d = lane; d < DD; d += 32) { float v = p[d]; s = fmaf(v, v, s); }
#pragma unroll
    for (int o = 16; o; o >>= 1) s += __shfl_xor_sync(0xffffffff, s, o);
    if (!lane) g_sf[row] = s;
}

__global__ void split_flat_kernel() {
    int i = blockIdx.x * 256 + threadIdx.x;
    if (i >= NN * DD / 4) return;
    float4 v = *(const float4*)&g_flat[i * 4];
    float xs[4] = {v.x, v.y, v.z, v.w};
#pragma unroll
    for (int j = 0; j < 4; j++) {
        __nv_bfloat16 hi = __float2bfloat16(xs[j]);
        __nv_bfloat16 lo = __float2bfloat16(xs[j] - __bfloat162float(hi));
        g_fhi[i * 4 + j] = hi;
        g_flo[i * 4 + j] = lo;
    }
}

__global__ void split_emb_kernel(const float* __restrict__ emb) {
    int i = blockIdx.x * 256 + threadIdx.x;
    if (i >= KK * DD / 4) return;
    float4 v = *(const float4*)&emb[i * 4];
    float xs[4] = {v.x, v.y, v.z, v.w};
#pragma unroll
    for (int j = 0; j < 4; j++) {
        __nv_bfloat16 hi = __float2bfloat16(xs[j]);
        __nv_bfloat16 lo = __float2bfloat16(xs[j] - __bfloat162float(hi));
        g_ehi[i * 4 + j] = hi;
        g_elo[i * 4 + j] = lo;
    }
}

// ---------------------------------------------------------------------------
// Kernel 3: distance GEMM + argmin, bf16 hi/lo 3-pass mma.sync.
// Fragment-hoisted inner loop (12 ldsm4 per k16), single barrier per stage,
// loads for s+1 issued after the stage-s barrier.
// ---------------------------------------------------------------------------
#define APITCH  528
#define BPITCH  80
#define AHI_OFF 0
#define ALO_OFF 67584          // 128*528
#define B_OFF   135168
#define BMAT_SZ 20480          // 256*80
#define BBUF_SZ 40960
#define DS_SMEM (B_OFF + 2 * BBUF_SZ)   // 217088
#define NSTAGE  256            // 32 col-tiles * 8 k-chunks

__device__ __forceinline__ void load_bstage(uint32_t sb, int buf, int s, int tid) {
    const int ct = s >> 3;
    const int k0 = (s & 7) * 32;
    uint32_t dst = sb + B_OFF + buf * BBUF_SZ;
    const char* srch = (const char*)g_ehi;
    const char* srcl = (const char*)g_elo;
    size_t gbase = (size_t)ct * 256 * 512 + (size_t)k0 * 2;
#pragma unroll
    for (int i = 0; i < 4; i++) {
        int c = i * 256 + tid;            // 0..1023
        int row = c >> 2, ch = c & 3;
        uint32_t doff = row * BPITCH + ch * 16;
        size_t soff = gbase + (size_t)row * 512 + ch * 16;
        CP_ASYNC16(dst + doff, srch + soff);
        CP_ASYNC16(dst + BMAT_SZ + doff, srcl + soff);
    }
}

__global__ void __launch_bounds__(256, 1) dist_kernel() {
    extern __shared__ char smem[];
    const uint32_t sb = smem_to_u32(smem);
    const int tid = threadIdx.x;
    const int l   = tid & 31;
    const int w   = tid >> 5;
    const int wm  = w >> 2;          // 0..1
    const int wn  = w & 3;           // 0..3
    const int r0  = blockIdx.x * 128;

    // Prologue: resident A hi/lo (4096 16B chunks each side) + first B stage
#pragma unroll 4
    for (int i = 0; i < 16; i++) {
        int c = i * 256 + tid;           // 0..4095
        int row = c >> 5, ch = c & 31;   // row 0..127, ch 0..31
        CP_ASYNC16(sb + AHI_OFF + row * APITCH + ch * 16,
                   (const char*)(g_fhi + (size_t)(r0 + row) * DD) + ch * 16);
        CP_ASYNC16(sb + ALO_OFF + row * APITCH + ch * 16,
                   (const char*)(g_flo + (size_t)(r0 + row) * DD) + ch * 16);
    }
    load_bstage(sb, 0, 0, tid);
    CP_COMMIT();

    // Per-thread invariant ldmatrix offsets
    const int arow = (l & 7) + ((l >> 3) & 1) * 8;
    const int aco  = (l >> 4);
    uint32_t aoff[4];
#pragma unroll
    for (int mt = 0; mt < 4; mt++)
        aoff[mt] = (wm * 64 + mt * 16 + arow) * APITCH + aco * 16;
    const int brow = (l & 7) + ((l >> 4) << 3);
    const int bco  = (l >> 3) & 1;
    uint32_t boff[4];
#pragma unroll
    for (int bt = 0; bt < 4; bt++)
        boff[bt] = (wn * 64 + bt * 16 + brow) * BPITCH + bco * 16;

    float sfv[4][2];
#pragma unroll
    for (int mt = 0; mt < 4; mt++)
#pragma unroll
        for (int h = 0; h < 2; h++)
            sfv[mt][h] = g_sf[r0 + wm * 64 + mt * 16 + (l >> 2) + h * 8];

    float acc[4][8][4];
#pragma unroll
    for (int mt = 0; mt < 4; mt++)
#pragma unroll
        for (int nt = 0; nt < 8; nt++)
#pragma unroll
            for (int q = 0; q < 4; q++) acc[mt][nt][q] = 0.0f;

    float best[4][2];
    int   bidx[4][2];
#pragma unroll
    for (int mt = 0; mt < 4; mt++)
#pragma unroll
        for (int h = 0; h < 2; h++) { best[mt][h] = FLT_MAX; bidx[mt][h] = 0; }

    for (int s = 0; s < NSTAGE; s++) {
        // Only load(s) is outstanding here; wait for it, then one barrier.
        CP_WAIT0();
        __syncthreads();
        // Prefetch stage s+1 (buffer (s+1)&1 — all readers passed the barrier)
        if (s + 1 < NSTAGE) {
            load_bstage(sb, (s + 1) & 1, s + 1, tid);
            CP_COMMIT();
        }

        const uint32_t bbase = sb + B_OFF + (s & 1) * BBUF_SZ;
        const int kc = (s & 7) * 4;       // A 16B-chunk base for this stage

#pragma unroll
        for (int kk = 0; kk < 2; kk++) {
            uint32_t ah[4][4], bx[4][4], al[4][4];
            // pass 0: A_hi x B_hi
#pragma unroll
            for (int mt = 0; mt < 4; mt++)
                ldsm4(sb + AHI_OFF + aoff[mt] + (kc + kk * 2) * 16, ah[mt]);
#pragma unroll
            for (int bt = 0; bt < 4; bt++)
                ldsm4(bbase + boff[bt] + kk * 32, bx[bt]);
#pragma unroll
            for (int mt = 0; mt < 4; mt++)
#pragma unroll
                for (int nt = 0; nt < 8; nt++)
                    mma16816(acc[mt][nt], ah[mt],
                             bx[nt >> 1][(nt & 1) * 2], bx[nt >> 1][(nt & 1) * 2 + 1]);
            // pass 1: A_lo x B_hi (B fragments reused)
#pragma unroll
            for (int mt = 0; mt < 4; mt++)
                ldsm4(sb + ALO_OFF + aoff[mt] + (kc + kk * 2) * 16, al[mt]);
#pragma unroll
            for (int mt = 0; mt < 4; mt++)
#pragma unroll
                for (int nt = 0; nt < 8; nt++)
                    mma16816(acc[mt][nt], al[mt],
                             bx[nt >> 1][(nt & 1) * 2], bx[nt >> 1][(nt & 1) * 2 + 1]);
            // pass 2: A_hi x B_lo (A_hi fragments reused, B overwritten)
#pragma unroll
            for (int bt = 0; bt < 4; bt++)
                ldsm4(bbase + BMAT_SZ + boff[bt] + kk * 32, bx[bt]);
#pragma unroll
            for (int mt = 0; mt < 4; mt++)
#pragma unroll
                for (int nt = 0; nt < 8; nt++)
                    mma16816(acc[mt][nt], ah[mt],
                             bx[nt >> 1][(nt & 1) * 2], bx[nt >> 1][(nt & 1) * 2 + 1]);
        }

        if ((s & 7) == 7) {
            const int ct = s >> 3;
#pragma unroll
            for (int nt = 0; nt < 8; nt++) {
#pragma unroll
                for (int q = 0; q < 2; q++) {
                    int col = ct * 256 + wn * 64 + nt * 8 + (l & 3) * 2 + q;
                    float se = __ldg(&g_se[col]);
#pragma unroll
                    for (int mt = 0; mt < 4; mt++)
#pragma unroll
                        for (int h = 0; h < 2; h++) {
                            float g  = acc[mt][nt][h * 2 + q];
                            float d2 = __fsub_rn(__fadd_rn(sfv[mt][h], se),
                                                 __fmul_rn(2.0f, g));
                            if (d2 < best[mt][h]) { best[mt][h] = d2; bidx[mt][h] = col; }
                            acc[mt][nt][h * 2 + q] = 0.0f;
                        }
                }
            }
        }
    }

    // Final per-row reduce (128 rows x 16 candidate threads), lexicographic
    __syncthreads();
    float* rv = (float*)smem;
    int*   ri = (int*)(smem + 128 * 16 * 4);
    const int slot = wn * 4 + (l & 3);
#pragma unroll
    for (int mt = 0; mt < 4; mt++)
#pragma unroll
        for (int h = 0; h < 2; h++) {
            int rl = wm * 64 + mt * 16 + (l >> 2) + h * 8;
            rv[rl * 16 + slot] = best[mt][h];
            ri[rl * 16 + slot] = bidx[mt][h];
        }
    __syncthreads();
    if (tid < 128) {
        float bv = rv[tid * 16];
        int   bi = ri[tid * 16];
#pragma unroll
        for (int t = 1; t < 16; t++) {
            float v = rv[tid * 16 + t];
            int  ix = ri[tid * 16 + t];
            if (v < bv || (v == bv && ix < bi)) { bv = v; bi = ix; }
        }
        g_idx[r0 + tid] = bi;
    }
}

// ---------------------------------------------------------------------------
// Kernel 4: gather emb[idx] -> NCHW output
// ---------------------------------------------------------------------------
__global__ void gather_kernel(const float* __restrict__ emb,
                              float* __restrict__ out) {
    __shared__ float T[256][33];
    const int b   = blockIdx.y;
    const int hw0 = blockIdx.x * 32;
    const int tid = threadIdx.x;
    for (int e = tid; e < 32 * 256; e += 256) {
        int nl = e >> 8, d = e & 255;
        int idx = g_idx[b * HWN + hw0 + nl];
        T[d][nl] = emb[(size_t)idx * DD + d];
    }
    __syncthreads();
    for (int e = tid; e < 32 * 256; e += 256) {
        int d = e >> 5, hl = e & 31;
        out[((size_t)(b * DD + d) << 10) + hw0 + hl] = T[d][hl];
    }
}

__global__ void idx_out_kernel(float* __restrict__ out) {
    int n = blockIdx.x * 256 + threadIdx.x;
    if (n < NN) out[4194304 + n] = (float)g_idx[n];
}

// ---------------------------------------------------------------------------
extern "C" void kernel_launch(void* const* d_in, const int* in_sizes, int n_in,
                              void* d_out, int out_size) {
    const float* z   = (const float*)d_in[0];
    const float* w   = (const float*)d_in[1];
    const float* bp  = (const float*)d_in[2];
    const float* emb = (const float*)d_in[3];
    float* out = (float*)d_out;

    cudaFuncSetAttribute(dist_kernel,
                         cudaFuncAttributeMaxDynamicSharedMemorySize, DS_SMEM);

    proj_kernel<<<dim3(NN / 64, DD / 64), 256>>>(z, w, bp);
    se_kernel<<<KK / 8, 256>>>(emb);
    sf_kernel<<<NN / 8, 256>>>();
    split_flat_kernel<<<(NN * DD / 4) / 256, 256>>>();
    split_emb_kernel<<<(KK * DD / 4) / 256, 256>>>(emb);
    dist_kernel<<<NN / 128, 256, DS_SMEM>>>();
    gather_kernel<<<dim3(HWN / 32, BB), 256>>>(emb, out);
    if (out_size >= 4194304 + NN)
        idx_out_kernel<<<NN / 256, 256>>>(out);
}